// round 2
// baseline (speedup 1.0000x reference)
#include <cuda_runtime.h>
#include <cuda_bf16.h>

#define NF   256     // feature dim
#define DEG  32      // neighbors per node
#define MM   33      // subgraph size (target + neighbors)
#define BMAX 10240   // max batch (actual B=10000)

// Scratch (allocation-free: __device__ globals)
__device__ float g_mix[(size_t)BMAX * NF];
__device__ float g_c0[BMAX];

// ---------------------------------------------------------------------------
// Kernel A: per-target subgraph construction + weighted feature mix
// grid = B CTAs, 256 threads each
// ---------------------------------------------------------------------------
__global__ void __launch_bounds__(256) subgraph_kernel(
    const float* __restrict__ feat,   // [N_NODES, NF]
    const int*   __restrict__ adj,    // [N_NODES, DEG]
    const int*   __restrict__ bn,     // [B]
    int B)
{
    __shared__ int   s_ids[MM];
    __shared__ int   s_adj[MM][DEG];
    __shared__ unsigned long long s_row[MM];   // adjacency bitmask rows (bits 0..32)
    __shared__ int   s_valid[MM];
    __shared__ float s_c[MM];
    __shared__ float s_w[MM];

    const int b = blockIdx.x;
    const int t = threadIdx.x;

    // ---- phase 1: subgraph node ids s = [v, adj[v]] ----
    const int v = bn[b];
    if (t == 0)  s_ids[0] = v;
    if (t < DEG) s_ids[1 + t] = adj[(size_t)v * DEG + t];
    __syncthreads();

    // ---- phase 2: gather adjacency rows of all subgraph nodes + dedup ----
    for (int idx = t; idx < MM * DEG; idx += 256) {
        int i = idx >> 5, k = idx & 31;
        s_adj[i][k] = adj[(size_t)s_ids[i] * DEG + k];
    }
    if (t < MM) {
        int sj = s_ids[t];
        int dup = 0;
        for (int i = 0; i < t; i++) dup |= (s_ids[i] == sj);
        s_valid[t] = !dup;
    }
    __syncthreads();

    // ---- phase 3: membership bitmasks. warp w handles rows i = w, w+8, ...
    // lane j tests column j (is s[j] in adj[s[i]]?); column 32 done by lane 0.
    {
        const int lane = t & 31;
        const int w    = t >> 5;
        const int sj   = s_ids[lane];
        const int s32  = s_ids[32];
        for (int i = w; i < MM; i += 8) {
            const int* arow = s_adj[i];
            bool bit = false, bit32 = false;
            #pragma unroll
            for (int k = 0; k < DEG; k++) {
                int a = arow[k];             // smem broadcast
                bit   |= (a == sj);
                bit32 |= (a == s32);
            }
            unsigned m = __ballot_sync(0xffffffffu, bit);
            if (lane == 0)
                s_row[i] = (unsigned long long)m |
                           (bit32 ? (1ull << 32) : 0ull);
        }
    }
    __syncthreads();

    // ---- phase 4: apply validity masking to rows & columns ----
    if (t < MM) {
        unsigned long long vm = 0ull;
        #pragma unroll
        for (int i = 0; i < MM; i++)
            vm |= ((unsigned long long)(s_valid[i] != 0)) << i;
        s_row[t] = s_valid[t] ? (s_row[t] & vm) : 0ull;
    }
    __syncthreads();

    // ---- phase 5: in-degrees -> c = 1/sqrt(max(deg,1)) ----
    if (t < MM) {
        int cnt = 0;
        #pragma unroll
        for (int i = 0; i < MM; i++)
            cnt += (int)((s_row[i] >> t) & 1ull);
        float deg = (float)(cnt < 1 ? 1 : cnt);
        s_c[t] = rsqrtf(deg);
    }
    __syncthreads();

    // ---- phase 6: per-source weights w_src[i] = c_i * sum_{j in row_i} c_j ----
    if (t < MM) {
        unsigned long long m = s_row[t];
        float sum = 0.0f;
        while (m) {
            int j = __ffsll((long long)m) - 1;
            sum += s_c[j];
            m &= (m - 1);
        }
        s_w[t] = s_c[t] * sum;
    }
    __syncthreads();

    // ---- phase 7: mix[f] = sum_i w_src[i] * feat[s_i][f] (thread t owns f=t) ----
    {
        float acc = 0.0f;
        #pragma unroll
        for (int i = 0; i < MM; i++) {
            float wv = s_w[i];
            acc = fmaf(wv, feat[(size_t)s_ids[i] * NF + t], acc);
        }
        g_mix[(size_t)b * NF + t] = acc;
        if (t == 0) g_c0[b] = s_c[0];
    }
}

// ---------------------------------------------------------------------------
// Kernel B: out = relu(mix @ W + c0 * feat[batch_nodes])
// Classic 128x128 SGEMM tile, BK=16, 256 threads, 8x8 per-thread microtile.
// ---------------------------------------------------------------------------
#define BM 128
#define BN 128
#define BK 16

__global__ void __launch_bounds__(256) gemm_kernel(
    const float* __restrict__ W,      // [NF, NF] row-major (k, n)
    const float* __restrict__ feat,   // [N_NODES, NF]
    const int*   __restrict__ bn,     // [B]
    float*       __restrict__ out,    // [B, NF]
    int B)
{
    __shared__ float sA[BK][BM + 4];  // transposed A tile (+pad, keeps 16B align)
    __shared__ float sB[BK][BN];

    const int tid = threadIdx.x;
    const int bm0 = blockIdx.y * BM;
    const int bn0 = blockIdx.x * BN;
    const int tx  = tid & 15;         // 0..15 -> 8 cols each
    const int ty  = tid >> 4;         // 0..15 -> 8 rows each

    const int arow = tid >> 2;        // 0..63
    const int acol = (tid & 3) * 4;   // 0,4,8,12
    const int brow = tid >> 5;        // 0..7
    const int bcol = (tid & 31) * 4;  // 0..124

    float acc[8][8];
    #pragma unroll
    for (int m = 0; m < 8; m++)
        #pragma unroll
        for (int n = 0; n < 8; n++) acc[m][n] = 0.0f;

    for (int kk = 0; kk < NF; kk += BK) {
        // load A tile (mix): BM x BK, store transposed
        #pragma unroll
        for (int p = 0; p < 2; p++) {
            int r  = arow + p * 64;
            int gr = bm0 + r;
            float4 va = make_float4(0.f, 0.f, 0.f, 0.f);
            if (gr < B)
                va = *reinterpret_cast<const float4*>(
                         &g_mix[(size_t)gr * NF + kk + acol]);
            sA[acol + 0][r] = va.x;
            sA[acol + 1][r] = va.y;
            sA[acol + 2][r] = va.z;
            sA[acol + 3][r] = va.w;
        }
        // load W tile: BK x BN
        #pragma unroll
        for (int p = 0; p < 2; p++) {
            int r = brow + p * 8;
            float4 vb = *reinterpret_cast<const float4*>(
                            &W[(size_t)(kk + r) * NF + bn0 + bcol]);
            *reinterpret_cast<float4*>(&sB[r][bcol]) = vb;
        }
        __syncthreads();

        #pragma unroll
        for (int k = 0; k < BK; k++) {
            float ra[8], rb[8];
            #pragma unroll
            for (int m = 0; m < 8; m++) ra[m] = sA[k][ty * 8 + m];
            #pragma unroll
            for (int n = 0; n < 8; n++) rb[n] = sB[k][tx * 8 + n];
            #pragma unroll
            for (int m = 0; m < 8; m++)
                #pragma unroll
                for (int n = 0; n < 8; n++)
                    acc[m][n] = fmaf(ra[m], rb[n], acc[m][n]);
        }
        __syncthreads();
    }

    // epilogue: relu(acc + c0[row] * feat[bn[row]][col])
    #pragma unroll
    for (int m = 0; m < 8; m++) {
        int gr = bm0 + ty * 8 + m;
        if (gr >= B) continue;
        int   node = bn[gr];
        float cc   = g_c0[gr];
        const float* hrow = &feat[(size_t)node * NF];
        #pragma unroll
        for (int n = 0; n < 8; n++) {
            int gc = bn0 + tx * 8 + n;
            float val = acc[m][n] + cc * hrow[gc];
            out[(size_t)gr * NF + gc] = fmaxf(val, 0.0f);
        }
    }
}

// ---------------------------------------------------------------------------
extern "C" void kernel_launch(void* const* d_in, const int* in_sizes, int n_in,
                              void* d_out, int out_size)
{
    const float* feat = (const float*)d_in[0];   // node_features [50000,256]
    const float* W    = (const float*)d_in[1];   // weight [256,256]
    const int*   adj  = (const int*)d_in[2];     // adj [50000,32]
    const int*   bn   = (const int*)d_in[3];     // batch_nodes [B]
    float*       out  = (float*)d_out;

    const int B = in_sizes[3];

    subgraph_kernel<<<B, 256>>>(feat, adj, bn, B);

    dim3 grid(NF / BN, (B + BM - 1) / BM);
    gemm_kernel<<<grid, 256>>>(W, feat, bn, out, B);
}

// round 5
// speedup vs baseline: 1.2297x; 1.2297x over previous
#include <cuda_runtime.h>
#include <cuda_bf16.h>

#define NF   256     // feature dim
#define DEG  32      // neighbors per node
#define MM   33      // subgraph size (target + neighbors)
#define BMAX 10240   // max batch (actual B=10000)

// Scratch (allocation-free: __device__ globals)
__device__ __align__(16) float g_mix[(size_t)BMAX * NF];
__device__ float g_c0[BMAX];

// ---------------------------------------------------------------------------
// Kernel A: per-target subgraph construction + weighted feature mix
// grid = B CTAs, 256 threads each
// ---------------------------------------------------------------------------
__global__ void __launch_bounds__(256) subgraph_kernel(
    const float* __restrict__ feat,   // [N_NODES, NF]
    const int*   __restrict__ adj,    // [N_NODES, DEG]
    const int*   __restrict__ bn,     // [B]
    int B)
{
    __shared__ int   s_ids[MM];
    __shared__ __align__(16) int s_adj[MM][DEG];
    __shared__ unsigned long long s_row[MM];   // adjacency bitmask rows (bits 0..32)
    __shared__ int   s_valid[MM];
    __shared__ float s_c[MM];
    __shared__ float s_w[MM];
    __shared__ __align__(16) float4 s_acc[4][64];   // per-quad partial mix

    const int b = blockIdx.x;
    const int t = threadIdx.x;

    // ---- phase 1: subgraph node ids s = [v, adj[v]] ----
    const int v = bn[b];
    if (t == 0)  s_ids[0] = v;
    if (t < DEG) s_ids[1 + t] = adj[(size_t)v * DEG + t];
    __syncthreads();

    // ---- phase 2: gather adjacency rows (int4: 33 rows x 8 int4 = 264 loads)
    // NOTE: 264 > 256 threads -> strided loop, NOT a single guard.
    for (int idx = t; idx < MM * (DEG / 4); idx += 256) {
        int i = idx >> 3, q = idx & 7;
        int4 a4 = *reinterpret_cast<const int4*>(
                      &adj[(size_t)s_ids[i] * DEG + q * 4]);
        *reinterpret_cast<int4*>(&s_adj[i][q * 4]) = a4;
    }
    // dedup: valid[j] = no earlier occurrence of s[j]
    if (t < MM) {
        int sj = s_ids[t];
        int dup = 0;
        for (int i = 0; i < t; i++) dup |= (s_ids[i] == sj);
        s_valid[t] = !dup;
    }
    __syncthreads();

    // ---- phase 3: membership bitmasks. warp w handles rows i = w, w+8, ...
    {
        const int lane = t & 31;
        const int w    = t >> 5;
        const int sj   = s_ids[lane];
        const int s32  = s_ids[32];
        for (int i = w; i < MM; i += 8) {
            const int* arow = s_adj[i];
            bool bit = false, bit32 = false;
            #pragma unroll
            for (int k = 0; k < DEG; k++) {
                int a = arow[k];             // smem broadcast
                bit   |= (a == sj);
                bit32 |= (a == s32);
            }
            unsigned m = __ballot_sync(0xffffffffu, bit);
            if (lane == 0)
                s_row[i] = (unsigned long long)m |
                           (bit32 ? (1ull << 32) : 0ull);
        }
    }
    __syncthreads();

    // ---- phase 4: validity masking of rows & columns ----
    if (t < MM) {
        unsigned long long vm = 0ull;
        #pragma unroll
        for (int i = 0; i < MM; i++)
            vm |= ((unsigned long long)(s_valid[i] != 0)) << i;
        s_row[t] = s_valid[t] ? (s_row[t] & vm) : 0ull;
    }
    __syncthreads();

    // ---- phase 5: in-degrees -> c = 1/sqrt(max(deg,1)) ----
    if (t < MM) {
        int cnt = 0;
        #pragma unroll
        for (int i = 0; i < MM; i++)
            cnt += (int)((s_row[i] >> t) & 1ull);
        float deg = (float)(cnt < 1 ? 1 : cnt);
        s_c[t] = rsqrtf(deg);
    }
    __syncthreads();

    // ---- phase 6: w_src[i] = c_i * sum_{j in row_i} c_j ----
    if (t < MM) {
        unsigned long long m = s_row[t];
        float sum = 0.0f;
        while (m) {
            int j = __ffsll((long long)m) - 1;
            sum += s_c[j];
            m &= (m - 1);
        }
        s_w[t] = s_c[t] * sum;
    }
    __syncthreads();

    // ---- phase 7: mix = sum_i w_i * feat[s_i]  (float4, quad-partitioned) ----
    // quad q = t>>6 accumulates rows i = q, q+4, ...; 64 threads cover the row.
    {
        const int q = t >> 6;        // 0..3
        const int j = t & 63;        // float4 index within row
        float4 acc = make_float4(0.f, 0.f, 0.f, 0.f);
        for (int i = q; i < MM; i += 4) {
            float wv = s_w[i];
            float4 f4 = *reinterpret_cast<const float4*>(
                            &feat[(size_t)s_ids[i] * NF + j * 4]);
            acc.x = fmaf(wv, f4.x, acc.x);
            acc.y = fmaf(wv, f4.y, acc.y);
            acc.z = fmaf(wv, f4.z, acc.z);
            acc.w = fmaf(wv, f4.w, acc.w);
        }
        s_acc[q][j] = acc;
    }
    __syncthreads();

    if (t < 64) {
        float4 a0 = s_acc[0][t], a1 = s_acc[1][t];
        float4 a2 = s_acc[2][t], a3 = s_acc[3][t];
        float4 r;
        r.x = (a0.x + a1.x) + (a2.x + a3.x);
        r.y = (a0.y + a1.y) + (a2.y + a3.y);
        r.z = (a0.z + a1.z) + (a2.z + a3.z);
        r.w = (a0.w + a1.w) + (a2.w + a3.w);
        *reinterpret_cast<float4*>(&g_mix[(size_t)b * NF + t * 4]) = r;
        if (t == 0) g_c0[b] = s_c[0];
    }
}

// ---------------------------------------------------------------------------
// Kernel B: out = relu(mix @ W + c0 * feat[batch_nodes])
// 64x128 tile, BK=16, 256 threads, 8x4 per-thread microtile.
// grid = (2, ceil(B/64)) = 314 CTAs -> 3-4 CTAs/SM.
// ---------------------------------------------------------------------------
#define BM 64
#define BN 128
#define BK 16

__global__ void __launch_bounds__(256) gemm_kernel(
    const float* __restrict__ W,      // [NF, NF] row-major (k, n)
    const float* __restrict__ feat,   // [N_NODES, NF]
    const int*   __restrict__ bn,     // [B]
    float*       __restrict__ out,    // [B, NF]
    int B)
{
    __shared__ __align__(16) float sA[BK][BM];   // transposed A tile
    __shared__ __align__(16) float sB[BK][BN];

    const int tid = threadIdx.x;
    const int bm0 = blockIdx.y * BM;
    const int bn0 = blockIdx.x * BN;
    const int ty  = tid >> 5;         // 0..7  -> rows ty*8 .. +7
    const int tx  = tid & 31;         // 0..31 -> cols tx*4 .. +3

    const int arow = tid >> 2;        // 0..63
    const int acol = (tid & 3) * 4;   // 0,4,8,12
    const int brow = tid >> 5;        // 0..7  (and +8)
    const int bcol = (tid & 31) * 4;  // 0..124

    float acc[8][4];
    #pragma unroll
    for (int m = 0; m < 8; m++)
        #pragma unroll
        for (int n = 0; n < 4; n++) acc[m][n] = 0.0f;

    for (int kk = 0; kk < NF; kk += BK) {
        // A tile (mix): 64 x 16, one float4 per thread, stored transposed
        {
            int gr = bm0 + arow;
            float4 va = make_float4(0.f, 0.f, 0.f, 0.f);
            if (gr < B)
                va = *reinterpret_cast<const float4*>(
                         &g_mix[(size_t)gr * NF + kk + acol]);
            sA[acol + 0][arow] = va.x;
            sA[acol + 1][arow] = va.y;
            sA[acol + 2][arow] = va.z;
            sA[acol + 3][arow] = va.w;
        }
        // W tile: 16 x 128, two float4 per thread
        #pragma unroll
        for (int p = 0; p < 2; p++) {
            int r = brow + p * 8;
            float4 vb = *reinterpret_cast<const float4*>(
                            &W[(size_t)(kk + r) * NF + bn0 + bcol]);
            *reinterpret_cast<float4*>(&sB[r][bcol]) = vb;
        }
        __syncthreads();

        #pragma unroll
        for (int k = 0; k < BK; k++) {
            float4 ra0 = *reinterpret_cast<const float4*>(&sA[k][ty * 8 + 0]);
            float4 ra1 = *reinterpret_cast<const float4*>(&sA[k][ty * 8 + 4]);
            float4 rb  = *reinterpret_cast<const float4*>(&sB[k][tx * 4]);
            float ra[8] = {ra0.x, ra0.y, ra0.z, ra0.w, ra1.x, ra1.y, ra1.z, ra1.w};
            float rn[4] = {rb.x, rb.y, rb.z, rb.w};
            #pragma unroll
            for (int m = 0; m < 8; m++)
                #pragma unroll
                for (int n = 0; n < 4; n++)
                    acc[m][n] = fmaf(ra[m], rn[n], acc[m][n]);
        }
        __syncthreads();
    }

    // epilogue: relu(acc + c0[row] * feat[bn[row]][col]), float4 stores
    #pragma unroll
    for (int m = 0; m < 8; m++) {
        int gr = bm0 + ty * 8 + m;
        if (gr >= B) continue;
        int   node = bn[gr];
        float cc   = g_c0[gr];
        int   gc   = bn0 + tx * 4;
        float4 h4 = *reinterpret_cast<const float4*>(
                        &feat[(size_t)node * NF + gc]);
        float4 r;
        r.x = fmaxf(acc[m][0] + cc * h4.x, 0.0f);
        r.y = fmaxf(acc[m][1] + cc * h4.y, 0.0f);
        r.z = fmaxf(acc[m][2] + cc * h4.z, 0.0f);
        r.w = fmaxf(acc[m][3] + cc * h4.w, 0.0f);
        *reinterpret_cast<float4*>(&out[(size_t)gr * NF + gc]) = r;
    }
}

// ---------------------------------------------------------------------------
extern "C" void kernel_launch(void* const* d_in, const int* in_sizes, int n_in,
                              void* d_out, int out_size)
{
    const float* feat = (const float*)d_in[0];   // node_features [50000,256]
    const float* W    = (const float*)d_in[1];   // weight [256,256]
    const int*   adj  = (const int*)d_in[2];     // adj [50000,32]
    const int*   bn   = (const int*)d_in[3];     // batch_nodes [B]
    float*       out  = (float*)d_out;

    const int B = in_sizes[3];

    subgraph_kernel<<<B, 256>>>(feat, adj, bn, B);

    dim3 grid(NF / BN, (B + BM - 1) / BM);
    gemm_kernel<<<grid, 256>>>(W, feat, bn, out, B);
}